// round 1
// baseline (speedup 1.0000x reference)
#include <cuda_runtime.h>
#include <cuda_bf16.h>
#include <stdint.h>

// ---------------------------------------------------------------------------
// GenNCA: 64-step neural cellular automaton, fully fused per step.
//   Fusion: conv0/conv1 + fc0 folded into ONE 3x3 conv 32->128 (weights M),
//   then ReLU, fc1 128->32, threefry mask, residual.
// ---------------------------------------------------------------------------

#define B_ 8
#define C_ 32
#define HW_ 128
#define HID_ 128
#define STEPS_ 64
#define PLANE_ (B_ * C_ * HW_ * HW_)   // 4,194,304 floats

// State ping-pong buffers (device-global scratch: allocation rules forbid cudaMalloc)
__device__ float g_buf[2][PLANE_];
// Folded conv weights M[k=9][cin=32][hid=128]
__device__ float g_M[9 * 32 * 128];
// Folded bias for hidden layer
__device__ float g_bp[128];
// fc1 transposed: W1T[h=128][o=32]
__device__ float g_W1T[128 * 32];
// 64 step keys (pairs)
__device__ unsigned g_keys[2 * STEPS_];

// ---------------------------------------------------------------------------
// Threefry-2x32 (20 rounds), bit-exact with JAX
// ---------------------------------------------------------------------------
__device__ __forceinline__ void threefry2x32(unsigned k0, unsigned k1,
                                             unsigned x0, unsigned x1,
                                             unsigned& o0, unsigned& o1) {
    unsigned ks2 = k0 ^ k1 ^ 0x1BD11BDAu;
#define TF_ROUND(r) { x0 += x1; x1 = __funnelshift_l(x1, x1, (r)); x1 ^= x0; }
    x0 += k0; x1 += k1;
    TF_ROUND(13) TF_ROUND(15) TF_ROUND(26) TF_ROUND(6)
    x0 += k1; x1 += ks2 + 1u;
    TF_ROUND(17) TF_ROUND(29) TF_ROUND(16) TF_ROUND(24)
    x0 += ks2; x1 += k0 + 2u;
    TF_ROUND(13) TF_ROUND(15) TF_ROUND(26) TF_ROUND(6)
    x0 += k0; x1 += k1 + 3u;
    TF_ROUND(17) TF_ROUND(29) TF_ROUND(16) TF_ROUND(24)
    x0 += k1; x1 += ks2 + 4u;
    TF_ROUND(13) TF_ROUND(15) TF_ROUND(26) TF_ROUND(6)
    x0 += ks2; x1 += k0 + 5u;
#undef TF_ROUND
    o0 = x0; o1 = x1;
}

// JAX partitionable threefry random_bits (32-bit): per-element 64-bit counter,
// bits = out0 ^ out1. Then uniform in [0,1), mask = (u > 0.5).
__device__ __forceinline__ float mask_for(unsigned k0, unsigned k1, unsigned idx) {
    unsigned o0, o1;
    threefry2x32(k0, k1, 0u, idx, o0, o1);
    unsigned bits = o0 ^ o1;
    float u = __uint_as_float((bits >> 9) | 0x3f800000u) - 1.0f;
    return (u > 0.5f) ? 1.0f : 0.0f;
}

// ---------------------------------------------------------------------------
// Weight preparation (tiny, once per launch)
//   blocks 0..287: M[k][c][:]   block 288: bias, W1T, keys
// ---------------------------------------------------------------------------
__global__ void prep_weights(const float* __restrict__ fc0w, const float* __restrict__ fc0b,
                             const float* __restrict__ fc1w,
                             const float* __restrict__ p0w, const float* __restrict__ p0b,
                             const float* __restrict__ p1w, const float* __restrict__ p1b) {
    int bid = blockIdx.x;
    int t = threadIdx.x;  // 128 threads = hidden index
    if (bid < 288) {
        int k = bid >> 5, c = bid & 31;
        float acc = (k == 4) ? fc0w[t * 96 + c] : 0.0f;
        const float* w0 = &p0w[(k * 32 + c) * 32];
        const float* w1 = &p1w[(k * 32 + c) * 32];
        const float* f1 = &fc0w[t * 96 + 32];
        const float* f2 = &fc0w[t * 96 + 64];
#pragma unroll
        for (int o = 0; o < 32; o++) acc += w0[o] * f1[o] + w1[o] * f2[o];
        g_M[(k * 32 + c) * 128 + t] = acc;
    } else {
        float acc = fc0b[t];
        const float* f1 = &fc0w[t * 96 + 32];
        const float* f2 = &fc0w[t * 96 + 64];
#pragma unroll
        for (int o = 0; o < 32; o++) acc += p0b[o] * f1[o] + p1b[o] * f2[o];
        g_bp[t] = acc;
#pragma unroll
        for (int o = 0; o < 32; o++) g_W1T[t * 32 + o] = fc1w[o * 128 + t];
        if (t == 0) {
            // step keys: jax.random.split(key(42), 64), partitionable:
            // key_s = threefry((0,42),(0,s))
            for (unsigned s = 0; s < STEPS_; s++) {
                unsigned a, b;
                threefry2x32(0u, 42u, 0u, s, a, b);
                g_keys[2 * s] = a; g_keys[2 * s + 1] = b;
            }
        }
    }
}

// ---------------------------------------------------------------------------
// Init: NHWC input -> planar [b][c][h][w], with vector embedding in last 6 ch
// ---------------------------------------------------------------------------
__global__ void init_state(const float* __restrict__ x, const float* __restrict__ xvec,
                           const float* __restrict__ bptw, const float* __restrict__ bptb) {
    int tid = blockIdx.x * blockDim.x + threadIdx.x;  // planar index
    if (tid >= PLANE_) return;
    int w = tid & 127;
    int h = (tid >> 7) & 127;
    int c = (tid >> 14) & 31;
    int b = tid >> 19;
    float v;
    if (c >= 26) {
        int e = c - 26;
        v = bptw[b * 6 + e] * xvec[b * 6 + e] + bptb[b * 6 + e];
    } else {
        v = x[(((b << 7) + h) * 128 + w) * 32 + c];
    }
    g_buf[0][tid] = v;
}

// ---------------------------------------------------------------------------
// Final: planar -> NHWC into d_out
// ---------------------------------------------------------------------------
__global__ void final_out(float* __restrict__ out) {
    int tid = blockIdx.x * blockDim.x + threadIdx.x;  // NHWC index
    if (tid >= PLANE_) return;
    int c = tid & 31;
    int w = (tid >> 5) & 127;
    int h = (tid >> 12) & 127;
    int b = tid >> 19;
    out[tid] = g_buf[0][(((b << 5) + c) << 14) + (h << 7) + w];
}

// ---------------------------------------------------------------------------
// One NCA step: block = (row, batch), 256 threads.
//   Stage 1: GEMM  hidden[128px][128h] = sum_k x_shift @ M[k]  (+bias, ReLU)
//   Stage 2: GEMM  dx[128px][32o] = hidden @ W1T ; residual + mask
// Shared memory (floats):
//   sx   [3][32][130]  = 12480   (reflect-padded input rows, planar)
//   sMk  [32][128]     =  4096   (current k-slice of M)
//   sh   [128h][128px] = 16384   (hidden, transposed for fc1)
//   sW1  [128][32]     =  4096
//   sbp  [128], smask [128]
// total 37312 floats = 149248 bytes (dynamic smem, opt-in)
// ---------------------------------------------------------------------------
#define SMEM_FLOATS 37312
#define SMEM_BYTES (SMEM_FLOATS * 4)

__global__ void __launch_bounds__(256, 1) nca_step(int s) {
    extern __shared__ float sm[];
    float* sx = sm;                    // 12480
    float* sMk = sx + 12480;           // 4096
    float* sh = sMk + 4096;            // 16384
    float* sW1 = sh + 16384;           // 4096
    float* sbp = sW1 + 4096;           // 128
    float* smask = sbp + 128;          // 128

    const float* __restrict__ xin = g_buf[s & 1];
    float* __restrict__ xout = g_buf[(s & 1) ^ 1];

    const int t = threadIdx.x;
    const int row = blockIdx.x;
    const int b = blockIdx.y;

    // ---- load 3 reflect-padded rows (planar, float4 from gmem) ----
    for (int u = t; u < 3072; u += 256) {
        int dy = u >> 10;
        int rem = u & 1023;
        int c = rem >> 5;
        int w4 = (rem & 31) << 2;
        int r = row - 1 + dy;
        r = (r < 0) ? 1 : ((r > 127) ? 126 : r);
        const float4 v = *(const float4*)&xin[((((b << 5) + c) << 7) + r) * 128 + w4];
        float* d = &sx[(dy * 32 + c) * 130 + 1 + w4];
        d[0] = v.x; d[1] = v.y; d[2] = v.z; d[3] = v.w;
    }
    // ---- fc1 weights, bias, mask ----
    for (int u = t; u < 1024; u += 256)
        ((float4*)sW1)[u] = ((const float4*)g_W1T)[u];
    if (t < 128) {
        sbp[t] = g_bp[t];
        unsigned idx = (unsigned)((((b << 7) + row) << 7) + t);
        smask[t] = mask_for(g_keys[2 * s], g_keys[2 * s + 1], idx);
    }
    __syncthreads();
    // ---- reflect columns: sx[.][.][0] = col1, sx[.][.][129] = col126 ----
    if (t < 96) {
        float* rp = &sx[t * 130];
        rp[0] = rp[2];
        rp[129] = rp[127];
    }
    __syncthreads();

    // ---- main GEMM: 128px x 128h, K = 9*32. 8x8 register tile ----
    const int tx = t & 15;   // pixel base
    const int ty = t >> 4;   // hidden base (x8)
    float acc[8][8];
#pragma unroll
    for (int j = 0; j < 8; j++) {
        float bv = sbp[ty * 8 + j];
#pragma unroll
        for (int i = 0; i < 8; i++) acc[i][j] = bv;
    }

    for (int k = 0; k < 9; k++) {
        __syncthreads();  // previous slice consumed
        for (int u = t; u < 1024; u += 256)
            ((float4*)sMk)[u] = ((const float4*)g_M)[k * 1024 + u];
        __syncthreads();
        const float* sxr = &sx[(k / 3) * (32 * 130) + (k % 3)] + tx;
        const float* sMc = &sMk[ty * 8];
#pragma unroll 4
        for (int c = 0; c < 32; c++) {
            float a[8];
#pragma unroll
            for (int i = 0; i < 8; i++) a[i] = sxr[c * 130 + 16 * i];
            float4 b0 = *(const float4*)&sMc[c * 128];
            float4 b1 = *(const float4*)&sMc[c * 128 + 4];
            float bb[8] = {b0.x, b0.y, b0.z, b0.w, b1.x, b1.y, b1.z, b1.w};
#pragma unroll
            for (int i = 0; i < 8; i++)
#pragma unroll
                for (int j = 0; j < 8; j++) acc[i][j] += a[i] * bb[j];
        }
    }
    __syncthreads();
    // ---- ReLU + store hidden transposed [h][px] ----
#pragma unroll
    for (int i = 0; i < 8; i++)
#pragma unroll
        for (int j = 0; j < 8; j++)
            sh[(ty * 8 + j) * 128 + tx + 16 * i] = fmaxf(acc[i][j], 0.0f);
    __syncthreads();

    // ---- fc1: 128px x 32o, K=128. 4x4 register tile, all-float4 LDS ----
    const int tx2 = t & 31;  // pixel base (x4)
    const int to = t >> 5;   // out-ch base (x4)
    float a2[4][4];
#pragma unroll
    for (int p = 0; p < 4; p++)
#pragma unroll
        for (int q = 0; q < 4; q++) a2[p][q] = 0.0f;
#pragma unroll 4
    for (int h = 0; h < 128; h++) {
        float4 hv = *(const float4*)&sh[h * 128 + tx2 * 4];
        float4 wv = *(const float4*)&sW1[h * 32 + to * 4];
        float hh[4] = {hv.x, hv.y, hv.z, hv.w};
        float ww[4] = {wv.x, wv.y, wv.z, wv.w};
#pragma unroll
        for (int p = 0; p < 4; p++)
#pragma unroll
            for (int q = 0; q < 4; q++) a2[p][q] += hh[p] * ww[q];
    }

    // ---- residual + mask, write planar ----
    float4 mv = *(const float4*)&smask[tx2 * 4];
    float mm[4] = {mv.x, mv.y, mv.z, mv.w};
#pragma unroll
    for (int q = 0; q < 4; q++) {
        int o = to * 4 + q;
        const float* cx = &sx[(32 + o) * 130 + 1 + tx2 * 4];
        float4 ov;
        ov.x = cx[0] + a2[0][q] * mm[0];
        ov.y = cx[1] + a2[1][q] * mm[1];
        ov.z = cx[2] + a2[2][q] * mm[2];
        ov.w = cx[3] + a2[3][q] * mm[3];
        *(float4*)&xout[((((b << 5) + o) << 7) + row) * 128 + tx2 * 4] = ov;
    }
}

// ---------------------------------------------------------------------------
extern "C" void kernel_launch(void* const* d_in, const int* in_sizes, int n_in,
                              void* d_out, int out_size) {
    const float* x    = (const float*)d_in[0];
    const float* xvec = (const float*)d_in[1];
    const float* fc0w = (const float*)d_in[2];
    const float* fc0b = (const float*)d_in[3];
    const float* fc1w = (const float*)d_in[4];
    const float* p0w  = (const float*)d_in[5];
    const float* p0b  = (const float*)d_in[6];
    const float* p1w  = (const float*)d_in[7];
    const float* p1b  = (const float*)d_in[8];
    const float* bptw = (const float*)d_in[9];
    const float* bptb = (const float*)d_in[10];

    cudaFuncSetAttribute(nca_step, cudaFuncAttributeMaxDynamicSharedMemorySize, SMEM_BYTES);

    prep_weights<<<289, 128>>>(fc0w, fc0b, fc1w, p0w, p0b, p1w, p1b);
    init_state<<<PLANE_ / 256, 256>>>(x, xvec, bptw, bptb);
    for (int s = 0; s < STEPS_; s++) {
        nca_step<<<dim3(HW_, B_), 256, SMEM_BYTES>>>(s);
    }
    final_out<<<PLANE_ / 256, 256>>>((float*)d_out);
}

// round 8
// speedup vs baseline: 2.9126x; 2.9126x over previous
#include <cuda_runtime.h>
#include <cuda_bf16.h>
#include <stdint.h>

// ===========================================================================
// GenNCA via mma.sync.m16n8k16 bf16 (sm_80 PTX -> legal on plain sm_100).
// conv0|conv1|fc0 folded into one 3x3 conv 32->128 (M); relu; fc1; mask; +x.
// Operands split hi/lo bf16 (lo = exact residual, unscaled): 3 mma terms
// give ~17-bit effective mantissa. State master is fp32 (range-safe: the NCA
// state grows to ~1e5 over 64 steps, which overflowed fp16 in R5).
// ===========================================================================
#define STEPS_ 64
#define PLANE_ (8 * 32 * 128 * 128)

__device__ float    g_xf[2][PLANE_];          // fp32 master state, NHWC
__device__ unsigned short g_xq[2][PLANE_ * 2];// operand planes [px][hi32|lo32] bf16
__device__ float    g_Mf[288 * 128];          // folded weights [k][hid]
__device__ unsigned short g_B1h[128 * 296];   // hi  [n=hid][k=288 +pad]
__device__ uint2    g_B1l[18 * 16 * 32];      // lo fragments [kk][ntile][lane]
__device__ unsigned short g_B2h[32 * 136];    // fc1 hi [o][h +pad]
__device__ unsigned short g_B2l[32 * 136];    // fc1 lo
__device__ float    g_bp[128];
__device__ unsigned g_keys[2 * STEPS_];

// ---- smem byte offsets ----
#define SA_    0          // 3 slots x (hi 130*80 + lo 130*80)
#define SLOT_  20800
#define SALO_  10400
#define SB1_   62400      // 128 x 592
#define SB2H_  138176     // 32 x 272
#define SB2L_  146880
#define SHHI_  155584     // 128 x 272
#define SHLO_  190400
#define SBIAS_ 225216
#define SMASK_ 225728
#define SMEM_BYTES 226240

// ---------------------------------------------------------------------------
__device__ __forceinline__ uint32_t smem_u32(const void* p) {
    uint32_t a;
    asm("{ .reg .u64 t; cvta.to.shared.u64 t, %1; cvt.u32.u64 %0, t; }" : "=r"(a) : "l"(p));
    return a;
}
__device__ __forceinline__ void cp16(uint32_t dst, const void* src) {
    asm volatile("cp.async.cg.shared.global [%0], [%1], 16;" :: "r"(dst), "l"(src) : "memory");
}
#define CP_COMMIT() asm volatile("cp.async.commit_group;" ::: "memory")
#define CP_WAIT0()  asm volatile("cp.async.wait_group 0;" ::: "memory")
__device__ __forceinline__ void ldm4(uint32_t* d, uint32_t a) {
    asm volatile("ldmatrix.sync.aligned.m8n8.x4.shared.b16 {%0,%1,%2,%3}, [%4];"
                 : "=r"(d[0]), "=r"(d[1]), "=r"(d[2]), "=r"(d[3]) : "r"(a));
}
__device__ __forceinline__ void mmabf(float* c, const uint32_t* a, uint32_t b0, uint32_t b1) {
    asm volatile("mma.sync.aligned.m16n8k16.row.col.f32.bf16.bf16.f32 "
                 "{%0,%1,%2,%3}, {%4,%5,%6,%7}, {%8,%9}, {%0,%1,%2,%3};"
                 : "+f"(c[0]), "+f"(c[1]), "+f"(c[2]), "+f"(c[3])
                 : "r"(a[0]), "r"(a[1]), "r"(a[2]), "r"(a[3]), "r"(b0), "r"(b1));
}
__device__ __forceinline__ unsigned short bfhi(float v) {
    return __bfloat16_as_ushort(__float2bfloat16(v));
}
__device__ __forceinline__ unsigned short bflo(float v) {
    float h = __bfloat162float(__float2bfloat16(v));
    return __bfloat16_as_ushort(__float2bfloat16(v - h));
}
__device__ __forceinline__ uint32_t pack2(unsigned short a, unsigned short b) {
    return (uint32_t)a | ((uint32_t)b << 16);
}

// ---------------------------------------------------------------------------
__device__ __forceinline__ void threefry2x32(unsigned k0, unsigned k1,
                                             unsigned x0, unsigned x1,
                                             unsigned& o0, unsigned& o1) {
    unsigned ks2 = k0 ^ k1 ^ 0x1BD11BDAu;
#define TFR(r) { x0 += x1; x1 = __funnelshift_l(x1, x1, (r)); x1 ^= x0; }
    x0 += k0; x1 += k1;
    TFR(13) TFR(15) TFR(26) TFR(6)  x0 += k1;  x1 += ks2 + 1u;
    TFR(17) TFR(29) TFR(16) TFR(24) x0 += ks2; x1 += k0 + 2u;
    TFR(13) TFR(15) TFR(26) TFR(6)  x0 += k0;  x1 += k1 + 3u;
    TFR(17) TFR(29) TFR(16) TFR(24) x0 += k1;  x1 += ks2 + 4u;
    TFR(13) TFR(15) TFR(26) TFR(6)  x0 += ks2; x1 += k0 + 5u;
#undef TFR
    o0 = x0; o1 = x1;
}
__device__ __forceinline__ float mask_for(unsigned k0, unsigned k1, unsigned idx) {
    unsigned o0, o1;
    threefry2x32(k0, k1, 0u, idx, o0, o1);
    unsigned bits = o0 ^ o1;
    float u = __uint_as_float((bits >> 9) | 0x3f800000u) - 1.0f;
    return (u > 0.5f) ? 1.0f : 0.0f;
}

// ---------------------------------------------------------------------------
__global__ void prep1(const float* __restrict__ fc0w, const float* __restrict__ fc0b,
                      const float* __restrict__ p0w, const float* __restrict__ p0b,
                      const float* __restrict__ p1w, const float* __restrict__ p1b) {
    int bid = blockIdx.x, h = threadIdx.x;
    if (bid < 288) {
        int tap = bid >> 5, c = bid & 31;
        float acc = (tap == 4) ? fc0w[h * 96 + c] : 0.0f;
        const float* w0 = &p0w[bid * 32];
        const float* w1 = &p1w[bid * 32];
        const float* f1 = &fc0w[h * 96 + 32];
        const float* f2 = &fc0w[h * 96 + 64];
#pragma unroll
        for (int o = 0; o < 32; o++) acc += w0[o] * f1[o] + w1[o] * f2[o];
        g_Mf[bid * 128 + h] = acc;
    } else {
        float acc = fc0b[h];
        const float* f1 = &fc0w[h * 96 + 32];
        const float* f2 = &fc0w[h * 96 + 64];
#pragma unroll
        for (int o = 0; o < 32; o++) acc += p0b[o] * f1[o] + p1b[o] * f2[o];
        g_bp[h] = acc;
        if (h == 0)
            for (unsigned s = 0; s < STEPS_; s++) {
                unsigned a, b;
                threefry2x32(0u, 42u, 0u, s, a, b);
                g_keys[2 * s] = a; g_keys[2 * s + 1] = b;
            }
    }
}

__global__ void prep2(const float* __restrict__ fc1w) {
    int tid = blockIdx.x * 256 + threadIdx.x;
    if (tid < 36864) {                 // B1 hi: [n][k]
        int n = tid / 288, k = tid % 288;
        g_B1h[n * 296 + k] = bfhi(g_Mf[k * 128 + n]);
    } else if (tid < 46080) {          // B1 lo fragments
        int j = tid - 36864;
        int l = j & 31, ntile = (j >> 5) & 15, kk = j >> 9;
        int n = ntile * 8 + (l >> 2), k0 = kk * 16 + 2 * (l & 3);
        g_B1l[j] = make_uint2(
            pack2(bflo(g_Mf[k0 * 128 + n]),       bflo(g_Mf[(k0 + 1) * 128 + n])),
            pack2(bflo(g_Mf[(k0 + 8) * 128 + n]), bflo(g_Mf[(k0 + 9) * 128 + n])));
    } else if (tid < 50176) {          // B2: [o][h]
        int j = tid - 46080;
        int o = j >> 7, h = j & 127;
        float v = fc1w[j];
        g_B2h[o * 136 + h] = bfhi(v);
        g_B2l[o * 136 + h] = bflo(v);
    }
}

__global__ void init_state(const float* __restrict__ x, const float* __restrict__ xvec,
                           const float* __restrict__ bptw, const float* __restrict__ bptb) {
    int tid = blockIdx.x * blockDim.x + threadIdx.x;
    if (tid >= PLANE_) return;
    int c = tid & 31, b = tid >> 19;
    float v;
    if (c >= 26) {
        int e = c - 26;
        v = bptw[b * 6 + e] * xvec[b * 6 + e] + bptb[b * 6 + e];
    } else v = x[tid];
    g_xf[0][tid] = v;
    int p = tid >> 5;
    g_xq[0][p * 64 + c] = bfhi(v);
    g_xq[0][p * 64 + 32 + c] = bflo(v);
}

__global__ void final_out(float* __restrict__ out) {
    int tid = blockIdx.x * blockDim.x + threadIdx.x;
    if (tid >= PLANE_) return;
    out[tid] = g_xf[0][tid];
}

// ---------------------------------------------------------------------------
// Step kernel: block = (row-group of 8, batch), 256 threads (8 warps).
// ---------------------------------------------------------------------------
__global__ void __launch_bounds__(256, 1) nca_step(int s) {
    extern __shared__ char smem[];
    const uint32_t sb = smem_u32(smem);
    float* sbias = (float*)(smem + SBIAS_);
    float* smask = (float*)(smem + SMASK_);

    const int t = threadIdx.x, l = t & 31, wid = t >> 5;
    const int b = blockIdx.y, r0 = blockIdx.x * 8;
    const int mg = wid >> 2, ng = wid & 3;
    const int mg2 = wid >> 1, ng2 = wid & 1;

    const unsigned short* __restrict__ xq_in = g_xq[s & 1];
    unsigned short*       __restrict__ xq_out = g_xq[(s & 1) ^ 1];
    const float* __restrict__ xf_in = g_xf[s & 1];
    float*       __restrict__ xf_out = g_xf[(s & 1) ^ 1];

    // resident weights
    for (int u = t; u < 4736; u += 256) cp16(sb + SB1_ + u * 16, (const char*)g_B1h + u * 16);
    for (int u = t; u < 544; u += 256)  cp16(sb + SB2H_ + u * 16, (const char*)g_B2h + u * 16);
    for (int u = t; u < 544; u += 256)  cp16(sb + SB2L_ + u * 16, (const char*)g_B2l + u * 16);
    CP_COMMIT();
    if (t < 128) sbias[t] = g_bp[t];

    auto load_row = [&](int r) {
        int slot = (r + 3) % 3;
        int src = r < 0 ? 1 : (r > 127 ? 126 : r);
        const char* base = (const char*)xq_in + (size_t)(((b << 7) + src) << 7) * 128;
        uint32_t d0 = sb + SA_ + (uint32_t)slot * SLOT_;
        for (int u = t; u < 1040; u += 256) {
            int p, sp, c8;
            if (u < 1024)      { p = (u >> 3) + 1; sp = u >> 3; c8 = u & 7; }
            else if (u < 1032) { p = 0;   sp = 1;   c8 = u - 1024; }
            else               { p = 129; sp = 126; c8 = u - 1032; }
            uint32_t dst = d0 + (uint32_t)p * 80 +
                           (c8 < 4 ? (uint32_t)c8 * 16 : SALO_ + (uint32_t)(c8 - 4) * 16);
            cp16(dst, base + sp * 128 + c8 * 16);
        }
        CP_COMMIT();
    };
    load_row(r0 - 1); load_row(r0); load_row(r0 + 1);

    const unsigned key0 = g_keys[2 * s], key1 = g_keys[2 * s + 1];
    const uint32_t aoff  = (uint32_t)(l & 15) * 80 + (uint32_t)(l >> 4) * 16;
    const uint32_t b1off = sb + SB1_ + (uint32_t)(ng * 32 + ((l >> 4) << 3) + (l & 7)) * 592
                         + (uint32_t)((l >> 3) & 1) * 16;
    const uint32_t hoff  = sb + SHHI_ + (uint32_t)(mg2 * 32 + (l & 15)) * 272 + (uint32_t)(l >> 4) * 16;
    const uint32_t b2off = sb + SB2H_ + (uint32_t)(ng2 * 16 + ((l >> 4) << 3) + (l & 7)) * 272
                         + (uint32_t)((l >> 3) & 1) * 16;

    for (int r = r0; r < r0 + 8; r++) {
        CP_WAIT0();
        __syncthreads();
        if (t < 128) smask[t] = mask_for(key0, key1, (unsigned)((((b << 7) + r) << 7) + t));

        // ================= GEMM1: 128px x 128hid, K=288 =================
        float c1[4][4][4];
#pragma unroll
        for (int mt = 0; mt < 4; mt++)
#pragma unroll
            for (int nt = 0; nt < 4; nt++)
#pragma unroll
                for (int i = 0; i < 4; i++) c1[mt][nt][i] = 0.0f;

#pragma unroll 1
        for (int dy = 0; dy < 3; dy++) {
            uint32_t slotb = sb + SA_ + (uint32_t)((r - 1 + dy + 3) % 3) * SLOT_;
#pragma unroll 1
            for (int dx = 0; dx < 3; dx++) {
                uint32_t abase = slotb + (uint32_t)(mg * 64 + dx) * 80 + aoff;
                int tap2 = (dy * 3 + dx) * 2;
#pragma unroll
                for (int k2 = 0; k2 < 2; k2++) {
                    int kk = tap2 + k2;
                    uint32_t ah[4][4], al[4][4], bh[2][4];
                    uint2 bl[4];
#pragma unroll
                    for (int mt = 0; mt < 4; mt++) {
                        ldm4(ah[mt], abase + (uint32_t)mt * 1280 + (uint32_t)k2 * 32);
                        ldm4(al[mt], abase + SALO_ + (uint32_t)mt * 1280 + (uint32_t)k2 * 32);
                    }
                    ldm4(bh[0], b1off + (uint32_t)kk * 32);
                    ldm4(bh[1], b1off + 16 * 592 + (uint32_t)kk * 32);
#pragma unroll
                    for (int nt = 0; nt < 4; nt++)
                        bl[nt] = __ldg(&g_B1l[(kk * 16 + ng * 4 + nt) * 32 + l]);
                    // term1: hi*hi
#pragma unroll
                    for (int mt = 0; mt < 4; mt++)
#pragma unroll
                        for (int nt = 0; nt < 4; nt++)
                            mmabf(c1[mt][nt], ah[mt], bh[nt >> 1][(nt & 1) * 2], bh[nt >> 1][(nt & 1) * 2 + 1]);
                    // term2: lo_a*hi_b (lo stored unscaled: exact)
#pragma unroll
                    for (int mt = 0; mt < 4; mt++)
#pragma unroll
                        for (int nt = 0; nt < 4; nt++)
                            mmabf(c1[mt][nt], al[mt], bh[nt >> 1][(nt & 1) * 2], bh[nt >> 1][(nt & 1) * 2 + 1]);
                    // term3: hi_a*lo_b
#pragma unroll
                    for (int mt = 0; mt < 4; mt++)
#pragma unroll
                        for (int nt = 0; nt < 4; nt++)
                            mmabf(c1[mt][nt], ah[mt], bl[nt].x, bl[nt].y);
                }
            }
        }
        __syncthreads();                 // sA slot (r-1) free; smask visible
        if (r < r0 + 7) load_row(r + 2);

        // ---- epilogue1: bias+relu, split -> sH hi/lo ----
#pragma unroll
        for (int mt = 0; mt < 4; mt++) {
            int px = mg * 64 + mt * 16 + (l >> 2);
#pragma unroll
            for (int nt = 0; nt < 4; nt++) {
                int o = ng * 32 + nt * 8 + ((l & 3) << 1);
                float b0 = sbias[o], b1 = sbias[o + 1];
                float v0 = fmaxf(c1[mt][nt][0] + b0, 0.f), v1 = fmaxf(c1[mt][nt][1] + b1, 0.f);
                float v2 = fmaxf(c1[mt][nt][2] + b0, 0.f), v3 = fmaxf(c1[mt][nt][3] + b1, 0.f);
                *(uint32_t*)(smem + SHHI_ + px * 272 + o * 2) = pack2(bfhi(v0), bfhi(v1));
                *(uint32_t*)(smem + SHHI_ + (px + 8) * 272 + o * 2) = pack2(bfhi(v2), bfhi(v3));
                *(uint32_t*)(smem + SHLO_ + px * 272 + o * 2) = pack2(bflo(v0), bflo(v1));
                *(uint32_t*)(smem + SHLO_ + (px + 8) * 272 + o * 2) = pack2(bflo(v2), bflo(v3));
            }
        }
        __syncthreads();                 // sH ready

        // ================= GEMM2: 128px x 32out, K=128 =================
        float c2[2][2][4];
#pragma unroll
        for (int mt = 0; mt < 2; mt++)
#pragma unroll
            for (int nt = 0; nt < 2; nt++)
#pragma unroll
                for (int i = 0; i < 4; i++) c2[mt][nt][i] = 0.0f;
#pragma unroll 1
        for (int kk = 0; kk < 8; kk++) {
            uint32_t ah[2][4], al[2][4], bh[4], blr[4];
#pragma unroll
            for (int mt = 0; mt < 2; mt++) {
                ldm4(ah[mt], hoff + (uint32_t)mt * (16 * 272) + (uint32_t)kk * 32);
                ldm4(al[mt], hoff + (SHLO_ - SHHI_) + (uint32_t)mt * (16 * 272) + (uint32_t)kk * 32);
            }
            ldm4(bh, b2off + (uint32_t)kk * 32);
            ldm4(blr, b2off + (SB2L_ - SB2H_) + (uint32_t)kk * 32);
#pragma unroll
            for (int mt = 0; mt < 2; mt++)
#pragma unroll
                for (int nt = 0; nt < 2; nt++) {
                    mmabf(c2[mt][nt], ah[mt], bh[nt * 2], bh[nt * 2 + 1]);
                    mmabf(c2[mt][nt], al[mt], bh[nt * 2], bh[nt * 2 + 1]);
                    mmabf(c2[mt][nt], ah[mt], blr[nt * 2], blr[nt * 2 + 1]);
                }
        }

        // ---- epilogue2: residual (fp32 master) + mask, write state ----
#pragma unroll
        for (int mt = 0; mt < 2; mt++) {
            int px = mg2 * 32 + mt * 16 + (l >> 2);
            float m0 = smask[px], m1 = smask[px + 8];
            uint32_t pbase = (uint32_t)(((((b << 7) + r) << 7) + px) << 5);
#pragma unroll
            for (int nt = 0; nt < 2; nt++) {
                int o = ng2 * 16 + nt * 8 + ((l & 3) << 1);
                float2 x0 = *(const float2*)&xf_in[pbase + o];
                float2 x1 = *(const float2*)&xf_in[pbase + 256 + o];
                float n0 = x0.x + c2[mt][nt][0] * m0;
                float n1 = x0.y + c2[mt][nt][1] * m0;
                float n2 = x1.x + c2[mt][nt][2] * m1;
                float n3 = x1.y + c2[mt][nt][3] * m1;
                *(float2*)&xf_out[pbase + o] = make_float2(n0, n1);
                *(float2*)&xf_out[pbase + 256 + o] = make_float2(n2, n3);
                uint32_t gi = pbase + (uint32_t)(o >> 1);   // uint32 units: 32/pixel
                ((uint32_t*)xq_out)[gi]            = pack2(bfhi(n0), bfhi(n1));
                ((uint32_t*)xq_out)[gi + 16]       = pack2(bflo(n0), bflo(n1));
                ((uint32_t*)xq_out)[gi + 256]      = pack2(bfhi(n2), bfhi(n3));
                ((uint32_t*)xq_out)[gi + 256 + 16] = pack2(bflo(n2), bflo(n3));
            }
        }
    }
}

// ---------------------------------------------------------------------------
extern "C" void kernel_launch(void* const* d_in, const int* in_sizes, int n_in,
                              void* d_out, int out_size) {
    const float* x    = (const float*)d_in[0];
    const float* xvec = (const float*)d_in[1];
    const float* fc0w = (const float*)d_in[2];
    const float* fc0b = (const float*)d_in[3];
    const float* fc1w = (const float*)d_in[4];
    const float* p0w  = (const float*)d_in[5];
    const float* p0b  = (const float*)d_in[6];
    const float* p1w  = (const float*)d_in[7];
    const float* p1b  = (const float*)d_in[8];
    const float* bptw = (const float*)d_in[9];
    const float* bptb = (const float*)d_in[10];

    cudaFuncSetAttribute(nca_step, cudaFuncAttributeMaxDynamicSharedMemorySize, SMEM_BYTES);

    prep1<<<289, 128>>>(fc0w, fc0b, p0w, p0b, p1w, p1b);
    prep2<<<196, 256>>>(fc1w);
    init_state<<<PLANE_ / 256, 256>>>(x, xvec, bptw, bptb);
    for (int s = 0; s < STEPS_; s++)
        nca_step<<<dim3(16, 8), 256, SMEM_BYTES>>>(s);
    final_out<<<PLANE_ / 256, 256>>>((float*)d_out);
}